// round 1
// baseline (speedup 1.0000x reference)
#include <cuda_runtime.h>

// Problem constants
#define B_    8
#define CIN   128
#define COUT  128
#define NPTS  8192
#define KM    32
#define MODES 256
#define SPLITS 8
#define KCHUNK (NPTS / SPLITS)   // 1024

// Scratch (device globals: no allocation allowed)
__device__ float g_part[SPLITS * B_ * CIN * MODES];   // split-K partials for x_hat (8 MB)
__device__ float g_xhat[B_ * CIN * MODES];            // (b, c_in, modes)     1 MB
__device__ float g_W2[CIN * COUT * MODES];            // (i, o, k)           16.7 MB
__device__ float g_yhat[B_ * COUT * MODES];           // (b, c_out, modes)    1 MB

// ---------------------------------------------------------------------------
// Kernel 1: x_hat[b,c,k] = sum_n x[b,c,n] * wbases[b,n,k]   (split-K partials)
// A = x[b] (128 x 8192, n contiguous), B = wbases[b] (8192 x 256, k contiguous)
// Block tile 64x64, kt=16, 256 threads, 4x4 per-thread micro-tile.
// Grid: (8 tiles, 8 splits, 8 batches) = 512 blocks.
// ---------------------------------------------------------------------------
__global__ __launch_bounds__(256) void k1_gemm(const float* __restrict__ x,
                                               const float* __restrict__ wb) {
    const int mt = blockIdx.x >> 2;      // 0..1
    const int nt = blockIdx.x & 3;       // 0..3
    const int s  = blockIdx.y;
    const int b  = blockIdx.z;
    const int row0 = mt * 64, col0 = nt * 64;
    const int k0 = s * KCHUNK;

    __shared__ float As[16][65];                    // transposed, scalar-read (broadcast)
    __shared__ __align__(16) float Bs[16][64];      // as-is, float4-read

    const float* Ab = x  + (size_t)b * CIN * NPTS;
    const float* Bb = wb + (size_t)b * NPTS * MODES;

    const int tid  = threadIdx.x;
    const int arow = tid >> 2, acol = (tid & 3) << 2;   // A tile: 64 rows x 16 k
    const int brow = tid >> 4, bcol = (tid & 15) << 2;  // B tile: 16 k x 64 cols
    const int ty = tid >> 4, tx = tid & 15;

    float acc[4][4];
#pragma unroll
    for (int i = 0; i < 4; i++)
#pragma unroll
        for (int j = 0; j < 4; j++) acc[i][j] = 0.f;

    for (int kb = 0; kb < KCHUNK; kb += 16) {
        const int kg = k0 + kb;
        float4 av = *(const float4*)(Ab + (size_t)(row0 + arow) * NPTS + kg + acol);
        float4 bv = *(const float4*)(Bb + (size_t)(kg + brow) * MODES + col0 + bcol);
        __syncthreads();
        As[acol + 0][arow] = av.x;
        As[acol + 1][arow] = av.y;
        As[acol + 2][arow] = av.z;
        As[acol + 3][arow] = av.w;
        *(float4*)(&Bs[brow][bcol]) = bv;
        __syncthreads();
#pragma unroll
        for (int kk = 0; kk < 16; kk++) {
            const float a0 = As[kk][ty * 4 + 0];
            const float a1 = As[kk][ty * 4 + 1];
            const float a2 = As[kk][ty * 4 + 2];
            const float a3 = As[kk][ty * 4 + 3];
            const float4 bq = *(const float4*)(&Bs[kk][tx * 4]);
            acc[0][0] += a0 * bq.x; acc[0][1] += a0 * bq.y; acc[0][2] += a0 * bq.z; acc[0][3] += a0 * bq.w;
            acc[1][0] += a1 * bq.x; acc[1][1] += a1 * bq.y; acc[1][2] += a1 * bq.z; acc[1][3] += a1 * bq.w;
            acc[2][0] += a2 * bq.x; acc[2][1] += a2 * bq.y; acc[2][2] += a2 * bq.z; acc[2][3] += a2 * bq.w;
            acc[3][0] += a3 * bq.x; acc[3][1] += a3 * bq.y; acc[3][2] += a3 * bq.z; acc[3][3] += a3 * bq.w;
        }
    }

    float* outp = g_part + ((size_t)(s * B_ + b) * CIN + row0 + ty * 4) * MODES + col0 + tx * 4;
#pragma unroll
    for (int i = 0; i < 4; i++) {
        float4 v = make_float4(acc[i][0], acc[i][1], acc[i][2], acc[i][3]);
        *(float4*)(outp + (size_t)i * MODES) = v;
    }
}

// Deterministic split-K reduce: x_hat[i] = sum_s g_part[s][i]
__global__ __launch_bounds__(256) void k1_reduce() {
    const int i = blockIdx.x * 256 + threadIdx.x;
    float s = 0.f;
#pragma unroll
    for (int p = 0; p < SPLITS; p++) s += g_part[(size_t)p * (B_ * CIN * MODES) + i];
    g_xhat[i] = s;
}

// ---------------------------------------------------------------------------
// Kernel 2a: W2[r,k] = sum_j weights[r,j] * D[j,k]   (r = i*COUT + o, 16384 rows)
// Block: 64 rows, 256 threads = one k-column each, D column held in registers.
// ---------------------------------------------------------------------------
__global__ __launch_bounds__(256) void k2a_w2(const float* __restrict__ weights,
                                              const float* __restrict__ D) {
    __shared__ float ws[64][KM];   // 8 KB
    const int r0 = blockIdx.x * 64;
    const int k  = threadIdx.x;

    for (int idx = threadIdx.x; idx < 64 * KM; idx += 256)
        ws[idx >> 5][idx & 31] = weights[(size_t)r0 * KM + idx];

    float Dreg[KM];
#pragma unroll
    for (int j = 0; j < KM; j++) Dreg[j] = D[(size_t)j * MODES + k];
    __syncthreads();

    for (int r = 0; r < 64; r++) {
        float acc = 0.f;
#pragma unroll
        for (int j = 0; j < KM; j++) acc += ws[r][j] * Dreg[j];
        g_W2[(size_t)(r0 + r) * MODES + k] = acc;
    }
}

// ---------------------------------------------------------------------------
// Kernel 2b: y_hat[b,o,k] = sum_i x_hat[b,i,k] * W2[i,o,k]
// Block = (o-tile of 4, b); thread = k column. All accesses k-contiguous.
// ---------------------------------------------------------------------------
__global__ __launch_bounds__(256) void k2b_yhat() {
    const int o0 = blockIdx.x * 4;
    const int b  = blockIdx.y;
    const int k  = threadIdx.x;
    float acc[4] = {0.f, 0.f, 0.f, 0.f};
    const float* xh = g_xhat + (size_t)b * CIN * MODES + k;
    for (int i = 0; i < CIN; i++) {
        const float xv = xh[(size_t)i * MODES];
#pragma unroll
        for (int oo = 0; oo < 4; oo++)
            acc[oo] += xv * g_W2[((size_t)i * COUT + o0 + oo) * MODES + k];
    }
#pragma unroll
    for (int oo = 0; oo < 4; oo++)
        g_yhat[((size_t)b * COUT + o0 + oo) * MODES + k] = acc[oo];
}

// ---------------------------------------------------------------------------
// Kernel 3: y[b,c,n] = sum_k y_hat[b,c,k] * bases[b,n,k]   ("NT" GEMM)
// A = y_hat[b] (128 x 256, k contig), B = bases[b] (8192 x 256, k contig).
// Block tile 64(m) x 64(n), kt=16, 16 K-steps. Grid (128, 2, 8) = 2048 blocks.
// ---------------------------------------------------------------------------
__global__ __launch_bounds__(256) void k3_gemm(const float* __restrict__ bases,
                                               float* __restrict__ y) {
    const int nt = blockIdx.x;   // 0..127
    const int mt = blockIdx.y;   // 0..1
    const int b  = blockIdx.z;
    const int row0 = mt * 64, n0 = nt * 64;

    __shared__ float As[16][65];                 // transposed, scalar-read
    __shared__ __align__(16) float Bs[16][68];   // transposed, float4-read (68*4B keeps 16B align)

    const float* Ab = g_yhat + (size_t)b * COUT * MODES;
    const float* Bb = bases  + (size_t)b * NPTS * MODES;

    const int tid  = threadIdx.x;
    const int lrow = tid >> 2, lcol = (tid & 3) << 2;   // both tiles: 64 rows x 16 k
    const int ty = tid >> 4, tx = tid & 15;

    float acc[4][4];
#pragma unroll
    for (int i = 0; i < 4; i++)
#pragma unroll
        for (int j = 0; j < 4; j++) acc[i][j] = 0.f;

    for (int kt = 0; kt < MODES; kt += 16) {
        float4 av = *(const float4*)(Ab + (size_t)(row0 + lrow) * MODES + kt + lcol);
        float4 bv = *(const float4*)(Bb + (size_t)(n0 + lrow) * MODES + kt + lcol);
        __syncthreads();
        As[lcol + 0][lrow] = av.x;
        As[lcol + 1][lrow] = av.y;
        As[lcol + 2][lrow] = av.z;
        As[lcol + 3][lrow] = av.w;
        Bs[lcol + 0][lrow] = bv.x;
        Bs[lcol + 1][lrow] = bv.y;
        Bs[lcol + 2][lrow] = bv.z;
        Bs[lcol + 3][lrow] = bv.w;
        __syncthreads();
#pragma unroll
        for (int kk = 0; kk < 16; kk++) {
            const float a0 = As[kk][ty * 4 + 0];
            const float a1 = As[kk][ty * 4 + 1];
            const float a2 = As[kk][ty * 4 + 2];
            const float a3 = As[kk][ty * 4 + 3];
            const float4 bq = *(const float4*)(&Bs[kk][tx * 4]);
            acc[0][0] += a0 * bq.x; acc[0][1] += a0 * bq.y; acc[0][2] += a0 * bq.z; acc[0][3] += a0 * bq.w;
            acc[1][0] += a1 * bq.x; acc[1][1] += a1 * bq.y; acc[1][2] += a1 * bq.z; acc[1][3] += a1 * bq.w;
            acc[2][0] += a2 * bq.x; acc[2][1] += a2 * bq.y; acc[2][2] += a2 * bq.z; acc[2][3] += a2 * bq.w;
            acc[3][0] += a3 * bq.x; acc[3][1] += a3 * bq.y; acc[3][2] += a3 * bq.z; acc[3][3] += a3 * bq.w;
        }
    }

    float* outp = y + ((size_t)b * CIN + row0 + ty * 4) * NPTS + n0 + tx * 4;
#pragma unroll
    for (int i = 0; i < 4; i++) {
        float4 v = make_float4(acc[i][0], acc[i][1], acc[i][2], acc[i][3]);
        *(float4*)(outp + (size_t)i * NPTS) = v;
    }
}

// ---------------------------------------------------------------------------
extern "C" void kernel_launch(void* const* d_in, const int* in_sizes, int n_in,
                              void* d_out, int out_size) {
    const float* x       = (const float*)d_in[0];   // (8, 128, 8192)
    const float* wbases  = (const float*)d_in[1];   // (8, 8192, 256)
    const float* bases   = (const float*)d_in[2];   // (8, 8192, 256)
    const float* weights = (const float*)d_in[3];   // (128, 128, 32)
    const float* D       = (const float*)d_in[4];   // (32, 256)
    float* y = (float*)d_out;                       // (8, 128, 8192)

    k1_gemm<<<dim3(8, SPLITS, B_), 256>>>(x, wbases);
    k2a_w2<<<CIN * COUT / 64, 256>>>(weights, D);          // independent of k1
    k1_reduce<<<(B_ * CIN * MODES) / 256, 256>>>();
    k2b_yhat<<<dim3(COUT / 4, B_), 256>>>();
    k3_gemm<<<dim3(NPTS / 64, CIN / 64, B_), 256>>>(bases, y);
}

// round 3
// speedup vs baseline: 1.2661x; 1.2661x over previous
#include <cuda_runtime.h>
#include <cstdint>

// ---------------- problem constants ----------------
#define B_    8
#define CIN   128
#define COUT  128
#define NPTS  8192
#define KM    32
#define MODES 256
#define SPLIT1 8
#define KC    32          // K per chunk (fp32 elems)
#define NT_   64          // N tile

// ---------------- device scratch ----------------
__device__ float g_part[SPLIT1 * B_ * CIN * MODES];   // 8.4 MB
__device__ float g_xhat[B_ * CIN * MODES];
__device__ float g_W2[CIN * COUT * MODES];            // 16.8 MB
__device__ float g_yhat[B_ * COUT * MODES];
__device__ float g_wbT[B_ * MODES * NPTS];            // 64 MB

// ---------------- smem layout (bf16 tiles, row stride 40 bf16 = 80B) ----------------
#define SSTR   40
#define ABYTES (128 * SSTR * 2)                 // 10240
#define BBYTES (64 * SSTR * 2)                  // 5120
#define OFF_AH 0
#define OFF_AL (ABYTES)
#define OFF_BH (2 * ABYTES)
#define OFF_BL (2 * ABYTES + BBYTES)
#define STAGE  (2 * ABYTES + 2 * BBYTES)        // 30720
#define SMEMSZ (2 * STAGE)                      // 61440

__device__ __forceinline__ uint32_t smem_u32(const void* p) {
    uint32_t a;
    asm("{ .reg .u64 t; cvta.to.shared.u64 t, %1; cvt.u32.u64 %0, t; }" : "=r"(a) : "l"(p));
    return a;
}

// pack: low 16 bits = bf16(lo_arg), high 16 = bf16(hi_arg)
__device__ __forceinline__ uint32_t pk_bf16(float lo, float hi) {
    uint32_t r;
    asm("cvt.rn.bf16x2.f32 %0, %1, %2;" : "=r"(r) : "f"(hi), "f"(lo));
    return r;
}

// convert 8 consecutive fp32 to hi/lo bf16 and store as two 16B smem rows
__device__ __forceinline__ void cvt_store8(uint32_t hiA, uint32_t loA, float4 v0, float4 v1) {
    uint32_t h0 = pk_bf16(v0.x, v0.y);
    uint32_t h1 = pk_bf16(v0.z, v0.w);
    uint32_t h2 = pk_bf16(v1.x, v1.y);
    uint32_t h3 = pk_bf16(v1.z, v1.w);
    float r0 = v0.x - __uint_as_float(h0 << 16);
    float r1 = v0.y - __uint_as_float(h0 & 0xffff0000u);
    float r2 = v0.z - __uint_as_float(h1 << 16);
    float r3 = v0.w - __uint_as_float(h1 & 0xffff0000u);
    float r4 = v1.x - __uint_as_float(h2 << 16);
    float r5 = v1.y - __uint_as_float(h2 & 0xffff0000u);
    float r6 = v1.z - __uint_as_float(h3 << 16);
    float r7 = v1.w - __uint_as_float(h3 & 0xffff0000u);
    uint32_t l0 = pk_bf16(r0, r1), l1 = pk_bf16(r2, r3);
    uint32_t l2 = pk_bf16(r4, r5), l3 = pk_bf16(r6, r7);
    asm volatile("st.shared.v4.b32 [%0], {%1,%2,%3,%4};" :: "r"(hiA), "r"(h0), "r"(h1), "r"(h2), "r"(h3));
    asm volatile("st.shared.v4.b32 [%0], {%1,%2,%3,%4};" :: "r"(loA), "r"(l0), "r"(l1), "r"(l2), "r"(l3));
}

#define LDSM4(r, addr) \
    asm volatile("ldmatrix.sync.aligned.m8n8.x4.shared.b16 {%0,%1,%2,%3}, [%4];" \
        : "=r"((r)[0]), "=r"((r)[1]), "=r"((r)[2]), "=r"((r)[3]) : "r"(addr))
#define LDSM2(r, addr) \
    asm volatile("ldmatrix.sync.aligned.m8n8.x2.shared.b16 {%0,%1}, [%2];" \
        : "=r"((r)[0]), "=r"((r)[1]) : "r"(addr))
#define MMA(c, a, bq) \
    asm volatile("mma.sync.aligned.m16n8k16.row.col.f32.bf16.bf16.f32 " \
        "{%0,%1,%2,%3}, {%4,%5,%6,%7}, {%8,%9}, {%0,%1,%2,%3};" \
        : "+f"((c)[0]), "+f"((c)[1]), "+f"((c)[2]), "+f"((c)[3]) \
        : "r"((a)[0]), "r"((a)[1]), "r"((a)[2]), "r"((a)[3]), "r"((bq)[0]), "r"((bq)[1]))

// ---------------------------------------------------------------------------
// bf16x3 GEMM: C[128, nt*64+..] (+split offset) = sum_k A[m,k]*B[n,k]
// A rows and B rows are K-contiguous fp32. M=128 fixed, N tile 64, K chunk 32.
// ---------------------------------------------------------------------------
__global__ __launch_bounds__(256, 1) void gemm_bf16x3(
    const float* __restrict__ A, const float* __restrict__ B, float* __restrict__ C,
    int lda, int ldb, int ldc,
    long sA, long sB, long sCb, long sCs, int nChunks)
{
    extern __shared__ __align__(16) char smem[];
    const uint32_t sb = smem_u32(smem);
    const int tid = threadIdx.x, wid = tid >> 5, lane = tid & 31;
    const int nt = blockIdx.x, sp = blockIdx.y, b = blockIdx.z;
    const long k0 = (long)sp * nChunks * KC;

    const float* Ab = A + (long)b * sA + k0;
    const float* Bb = B + (long)b * sB + (long)nt * NT_ * ldb + k0;
    float* Cb = C + (long)b * sCb + (long)sp * sCs + (long)nt * NT_;

    // staging assignment
    const int arow = tid >> 1, akh = (tid & 1) * 16;
    const int brow = tid >> 2, bkh = (tid & 3) * 8;
    const float* ag = Ab + (long)arow * lda + akh;
    const float* bg = Bb + (long)brow * ldb + bkh;
    const uint32_t aSt = sb + (uint32_t)(arow * 80 + akh * 2);
    const uint32_t bSt = sb + (uint32_t)(brow * 80 + bkh * 2);

    // warp tiling: 4 m-warps x 2 n-warps, warp tile 32x32
    const int wm = wid >> 1, wn = wid & 1;
    const int l16 = lane & 15, lh = lane >> 4;       // A ldmatrix lanes
    const int l8 = lane & 7, bh2 = (lane >> 3) & 1;  // B ldmatrix lanes

    float c[2][4][4];
#pragma unroll
    for (int i = 0; i < 2; i++)
#pragma unroll
        for (int j = 0; j < 4; j++)
#pragma unroll
            for (int q = 0; q < 4; q++) c[i][j][q] = 0.f;

    float4 a0v, a1v, a2v, a3v, b0v, b1v;

    // prologue: chunk 0 -> buffer 0
    a0v = *(const float4*)(ag);      a1v = *(const float4*)(ag + 4);
    a2v = *(const float4*)(ag + 8);  a3v = *(const float4*)(ag + 12);
    b0v = *(const float4*)(bg);      b1v = *(const float4*)(bg + 4);
    cvt_store8(aSt + OFF_AH,      aSt + OFF_AL,      a0v, a1v);
    cvt_store8(aSt + OFF_AH + 16, aSt + OFF_AL + 16, a2v, a3v);
    cvt_store8(bSt + OFF_BH,      bSt + OFF_BL,      b0v, b1v);

    for (int i = 0; i < nChunks; i++) {
        __syncthreads();
        const int cur = i & 1;
        const bool more = (i + 1 < nChunks);
        if (more) {
            const float* ag2 = ag + (long)(i + 1) * KC;
            const float* bg2 = bg + (long)(i + 1) * KC;
            a0v = *(const float4*)(ag2);      a1v = *(const float4*)(ag2 + 4);
            a2v = *(const float4*)(ag2 + 8);  a3v = *(const float4*)(ag2 + 12);
            b0v = *(const float4*)(bg2);      b1v = *(const float4*)(bg2 + 4);
        }
        // compute chunk i from buffer cur
        const uint32_t base = sb + (uint32_t)(cur * STAGE);
#pragma unroll
        for (int h = 0; h < 2; h++) {
            uint32_t ahi[2][4], alo[2][4], bhi[4][2], blo[4][2];
            const uint32_t aAddr = base + OFF_AH + (uint32_t)((wm * 32 + l16) * 80 + (h * 16 + lh * 8) * 2);
            LDSM4(ahi[0], aAddr);
            LDSM4(ahi[1], aAddr + 16 * 80);
            LDSM4(alo[0], aAddr + (OFF_AL - OFF_AH));
            LDSM4(alo[1], aAddr + (OFF_AL - OFF_AH) + 16 * 80);
            const uint32_t bAddr = base + OFF_BH + (uint32_t)((wn * 32 + l8) * 80 + (h * 16 + bh2 * 8) * 2);
#pragma unroll
            for (int nn = 0; nn < 4; nn++) {
                LDSM2(bhi[nn], bAddr + nn * 8 * 80);
                LDSM2(blo[nn], bAddr + (OFF_BL - OFF_BH) + nn * 8 * 80);
            }
#pragma unroll
            for (int mt = 0; mt < 2; mt++)
#pragma unroll
                for (int nn = 0; nn < 4; nn++) {
                    MMA(c[mt][nn], ahi[mt], bhi[nn]);
                    MMA(c[mt][nn], ahi[mt], blo[nn]);
                    MMA(c[mt][nn], alo[mt], bhi[nn]);
                }
        }
        if (more) {
            const uint32_t st = sb + (uint32_t)(((i + 1) & 1) * STAGE) - sb;  // stage offset
            const uint32_t aS = aSt + ((i + 1) & 1) * STAGE;
            const uint32_t bS = bSt + ((i + 1) & 1) * STAGE;
            (void)st;
            cvt_store8(aS + OFF_AH,      aS + OFF_AL,      a0v, a1v);
            cvt_store8(aS + OFF_AH + 16, aS + OFF_AL + 16, a2v, a3v);
            cvt_store8(bS + OFF_BH,      bS + OFF_BL,      b0v, b1v);
        }
    }

    // epilogue: c layout per mma: rows (lane>>2, +8), cols (lane&3)*2, +1
    const int mrow = wm * 32 + (lane >> 2);
    const int ncol = wn * 32 + (lane & 3) * 2;
#pragma unroll
    for (int mt = 0; mt < 2; mt++)
#pragma unroll
        for (int nn = 0; nn < 4; nn++) {
            float* p = Cb + (long)(mrow + mt * 16) * ldc + ncol + nn * 8;
            *(float2*)p = make_float2(c[mt][nn][0], c[mt][nn][1]);
            *(float2*)(p + (long)8 * ldc) = make_float2(c[mt][nn][2], c[mt][nn][3]);
        }
}

// ---------------------------------------------------------------------------
// wbases (b, n, k) -> g_wbT (b, k, n)
// ---------------------------------------------------------------------------
__global__ __launch_bounds__(256) void transpose_wb(const float* __restrict__ wb,
                                                    float* __restrict__ out) {
    __shared__ float t[32][33];
    const int b = blockIdx.z;
    const int n0 = blockIdx.x * 32, k0 = blockIdx.y * 32;
    const int x = threadIdx.x, y = threadIdx.y;
    const float* in = wb + (long)b * NPTS * MODES;
    float* o = out + (long)b * MODES * NPTS;
#pragma unroll
    for (int j = 0; j < 32; j += 8) t[y + j][x] = in[(long)(n0 + y + j) * MODES + k0 + x];
    __syncthreads();
#pragma unroll
    for (int j = 0; j < 32; j += 8) o[(long)(k0 + y + j) * NPTS + n0 + x] = t[x][y + j];
}

// split-K reduce
__global__ __launch_bounds__(256) void k1_reduce() {
    const int i = blockIdx.x * 256 + threadIdx.x;
    float s = 0.f;
#pragma unroll
    for (int p = 0; p < SPLIT1; p++) s += g_part[(size_t)p * (B_ * CIN * MODES) + i];
    g_xhat[i] = s;
}

// W2[r,k] = sum_j weights[r,j] * D[j,k]
__global__ __launch_bounds__(256) void k2a_w2(const float* __restrict__ weights,
                                              const float* __restrict__ D) {
    __shared__ float ws[64][KM];
    const int r0 = blockIdx.x * 64;
    const int k  = threadIdx.x;
    for (int idx = threadIdx.x; idx < 64 * KM; idx += 256)
        ws[idx >> 5][idx & 31] = weights[(size_t)r0 * KM + idx];
    float Dreg[KM];
#pragma unroll
    for (int j = 0; j < KM; j++) Dreg[j] = D[(size_t)j * MODES + k];
    __syncthreads();
    for (int r = 0; r < 64; r++) {
        float acc = 0.f;
#pragma unroll
        for (int j = 0; j < KM; j++) acc += ws[r][j] * Dreg[j];
        g_W2[(size_t)(r0 + r) * MODES + k] = acc;
    }
}

// y_hat[b,o,k] = sum_i x_hat[b,i,k] * W2[i,o,k]   (batch-inner: W2 read once)
__global__ __launch_bounds__(256) void k2b_yhat() {
    const int o0 = blockIdx.x * 4;
    const int k  = threadIdx.x;
    float acc[B_][4];
#pragma unroll
    for (int b = 0; b < B_; b++)
#pragma unroll
        for (int oo = 0; oo < 4; oo++) acc[b][oo] = 0.f;
    for (int i = 0; i < CIN; i++) {
        float w[4];
#pragma unroll
        for (int oo = 0; oo < 4; oo++)
            w[oo] = g_W2[((size_t)i * COUT + o0 + oo) * MODES + k];
#pragma unroll
        for (int b = 0; b < B_; b++) {
            const float xv = g_xhat[((size_t)b * CIN + i) * MODES + k];
#pragma unroll
            for (int oo = 0; oo < 4; oo++) acc[b][oo] += xv * w[oo];
        }
    }
#pragma unroll
    for (int b = 0; b < B_; b++)
#pragma unroll
        for (int oo = 0; oo < 4; oo++)
            g_yhat[((size_t)b * COUT + o0 + oo) * MODES + k] = acc[b][oo];
}

// ---------------------------------------------------------------------------
extern "C" void kernel_launch(void* const* d_in, const int* in_sizes, int n_in,
                              void* d_out, int out_size) {
    const float* x       = (const float*)d_in[0];   // (8, 128, 8192)
    const float* wbases  = (const float*)d_in[1];   // (8, 8192, 256)
    const float* bases   = (const float*)d_in[2];   // (8, 8192, 256)
    const float* weights = (const float*)d_in[3];   // (128, 128, 32)
    const float* Dm      = (const float*)d_in[4];   // (32, 256)
    float* y = (float*)d_out;                       // (8, 128, 8192)

    cudaFuncSetAttribute(gemm_bf16x3, cudaFuncAttributeMaxDynamicSharedMemorySize, SMEMSZ);

    void *p_part, *p_wbT, *p_yhat;
    cudaGetSymbolAddress(&p_part, g_part);
    cudaGetSymbolAddress(&p_wbT,  g_wbT);
    cudaGetSymbolAddress(&p_yhat, g_yhat);

    transpose_wb<<<dim3(NPTS / 32, MODES / 32, B_), dim3(32, 8)>>>(wbases, (float*)p_wbT);
    k2a_w2<<<CIN * COUT / 64, 256>>>(weights, Dm);

    // Stage 1: x_hat = x @ wbases   (M=128, N=256 modes, K=8192; split-K=8)
    gemm_bf16x3<<<dim3(MODES / NT_, SPLIT1, B_), 256, SMEMSZ>>>(
        x, (const float*)p_wbT, (float*)p_part,
        NPTS, NPTS, MODES,
        (long)CIN * NPTS, (long)MODES * NPTS,
        (long)CIN * MODES, (long)B_ * CIN * MODES,
        (NPTS / SPLIT1) / KC);                      // 32 chunks
    k1_reduce<<<(B_ * CIN * MODES) / 256, 256>>>();

    // Stage 2
    k2b_yhat<<<COUT / 4, 256>>>();

    // Stage 3: y = y_hat @ bases^T  (M=128, N=8192, K=256)
    gemm_bf16x3<<<dim3(NPTS / NT_, 1, B_), 256, SMEMSZ>>>(
        (const float*)p_yhat, bases, y,
        MODES, MODES, NPTS,
        (long)COUT * MODES, (long)NPTS * MODES,
        (long)CIN * NPTS, 0L,
        MODES / KC);                                // 8 chunks
}

// round 4
// speedup vs baseline: 1.2989x; 1.0260x over previous
#include <cuda_runtime.h>
#include <cstdint>

// ---------------- problem constants ----------------
#define B_    8
#define CIN   128
#define COUT  128
#define NPTS  8192
#define KM    32
#define MODES 256
#define SPLIT1 16
#define KC    64          // K per chunk (fp32 elems)
#define NT_   128         // N tile
#define NTHR  512

// ---------------- device scratch ----------------
__device__ float g_part[SPLIT1 * B_ * CIN * MODES];   // 16.8 MB
__device__ float g_xhat[B_ * CIN * MODES];
__device__ float g_W2[CIN * COUT * MODES];            // 16.8 MB
__device__ float g_yhat[B_ * COUT * MODES];
__device__ float g_wbT[B_ * MODES * NPTS];            // 64 MB

// ---------------- smem layout: row stride 144B (64 bf16 = 128B + 16B pad) ----------------
#define RSTR   144
#define ABYT   (128 * RSTR)                    // 18432
#define OFF_AH 0
#define OFF_AL (ABYT)
#define OFF_BH (2 * ABYT)
#define OFF_BL (3 * ABYT)
#define STAGE  (4 * ABYT)                      // 73728
#define SMEMSZ (2 * STAGE)                     // 147456

__device__ __forceinline__ uint32_t smem_u32(const void* p) {
    uint32_t a;
    asm("{ .reg .u64 t; cvta.to.shared.u64 t, %1; cvt.u32.u64 %0, t; }" : "=r"(a) : "l"(p));
    return a;
}

// pack: low 16 = bf16(lo_arg), high 16 = bf16(hi_arg)
__device__ __forceinline__ uint32_t pk_bf16(float lo, float hi) {
    uint32_t r;
    asm("cvt.rn.bf16x2.f32 %0, %1, %2;" : "=r"(r) : "f"(hi), "f"(lo));
    return r;
}

// convert 8 consecutive fp32 to hi/lo bf16, store as 16B rows at hiA/loA
__device__ __forceinline__ void cvt_store8(uint32_t hiA, uint32_t loA, float4 v0, float4 v1) {
    uint32_t h0 = pk_bf16(v0.x, v0.y);
    uint32_t h1 = pk_bf16(v0.z, v0.w);
    uint32_t h2 = pk_bf16(v1.x, v1.y);
    uint32_t h3 = pk_bf16(v1.z, v1.w);
    float r0 = v0.x - __uint_as_float(h0 << 16);
    float r1 = v0.y - __uint_as_float(h0 & 0xffff0000u);
    float r2 = v0.z - __uint_as_float(h1 << 16);
    float r3 = v0.w - __uint_as_float(h1 & 0xffff0000u);
    float r4 = v1.x - __uint_as_float(h2 << 16);
    float r5 = v1.y - __uint_as_float(h2 & 0xffff0000u);
    float r6 = v1.z - __uint_as_float(h3 << 16);
    float r7 = v1.w - __uint_as_float(h3 & 0xffff0000u);
    uint32_t l0 = pk_bf16(r0, r1), l1 = pk_bf16(r2, r3);
    uint32_t l2 = pk_bf16(r4, r5), l3 = pk_bf16(r6, r7);
    asm volatile("st.shared.v4.b32 [%0], {%1,%2,%3,%4};" :: "r"(hiA), "r"(h0), "r"(h1), "r"(h2), "r"(h3));
    asm volatile("st.shared.v4.b32 [%0], {%1,%2,%3,%4};" :: "r"(loA), "r"(l0), "r"(l1), "r"(l2), "r"(l3));
}

#define LDSM4(r, addr) \
    asm volatile("ldmatrix.sync.aligned.m8n8.x4.shared.b16 {%0,%1,%2,%3}, [%4];" \
        : "=r"((r)[0]), "=r"((r)[1]), "=r"((r)[2]), "=r"((r)[3]) : "r"(addr))
#define MMA(c, a, bq) \
    asm volatile("mma.sync.aligned.m16n8k16.row.col.f32.bf16.bf16.f32 " \
        "{%0,%1,%2,%3}, {%4,%5,%6,%7}, {%8,%9}, {%0,%1,%2,%3};" \
        : "+f"((c)[0]), "+f"((c)[1]), "+f"((c)[2]), "+f"((c)[3]) \
        : "r"((a)[0]), "r"((a)[1]), "r"((a)[2]), "r"((a)[3]), "r"((bq)[0]), "r"((bq)[1]))

// ---------------------------------------------------------------------------
// bf16x3 GEMM: C[128, nt*128+..] (+split offset) = sum_k A[m,k]*B[n,k]
// Both operand rows K-contiguous fp32. CTA tile 128x128, warp tile 32x32,
// 16 warps (4m x 4n), K chunk 64, double-buffered smem.
// ---------------------------------------------------------------------------
__global__ __launch_bounds__(NTHR, 1) void gemm_bf16x3(
    const float* __restrict__ A, const float* __restrict__ B, float* __restrict__ C,
    int lda, int ldb, int ldc,
    long sA, long sB, long sCb, long sCs, int nChunks)
{
    extern __shared__ __align__(16) char smem[];
    const uint32_t sb = smem_u32(smem);
    const int tid = threadIdx.x, wid = tid >> 5, lane = tid & 31;
    const int nt = blockIdx.x, sp = blockIdx.y, b = blockIdx.z;
    const long k0 = (long)sp * nChunks * KC;

    const float* Ab = A + (long)b * sA + k0;
    const float* Bb = B + (long)b * sB + (long)nt * NT_ * ldb + k0;
    float* Cb = C + (long)b * sCb + (long)sp * sCs + (long)nt * NT_;

    // staging: 512 threads cover 128 rows x 64 k (16 floats each)
    const int srow = tid >> 2, sk = (tid & 3) * 16;
    const float* ag = Ab + (long)srow * lda + sk;
    const float* bg = Bb + (long)srow * ldb + sk;
    const uint32_t sOff = (uint32_t)(srow * RSTR + sk * 2);

    // warp tiling: 4m x 4n, warp tile 32x32
    const int wm = wid >> 2, wn = wid & 3;
    // A ldmatrix lanes: 0-15 rows m, 16-31 rows m (k+8)
    const int l16 = lane & 15, lh = lane >> 4;
    // B ldmatrix x4 lanes: g0 (n0-7,k0), g1 (n0-7,k8), g2 (n8-15,k0), g3 (n8-15,k8)
    const int bn = ((lane >> 4) & 1) * 8 + (lane & 7);
    const int bk = ((lane >> 3) & 1) * 8;

    float c[2][4][4];
#pragma unroll
    for (int i = 0; i < 2; i++)
#pragma unroll
        for (int j = 0; j < 4; j++)
#pragma unroll
            for (int q = 0; q < 4; q++) c[i][j][q] = 0.f;

    float4 av[4], bv[4];

    // prologue: chunk 0 -> buffer 0
#pragma unroll
    for (int g = 0; g < 4; g++) { av[g] = *(const float4*)(ag + g * 4); bv[g] = *(const float4*)(bg + g * 4); }
    cvt_store8(sb + OFF_AH + sOff,      sb + OFF_AL + sOff,      av[0], av[1]);
    cvt_store8(sb + OFF_AH + sOff + 16, sb + OFF_AL + sOff + 16, av[2], av[3]);
    cvt_store8(sb + OFF_BH + sOff,      sb + OFF_BL + sOff,      bv[0], bv[1]);
    cvt_store8(sb + OFF_BH + sOff + 16, sb + OFF_BL + sOff + 16, bv[2], bv[3]);

    for (int i = 0; i < nChunks; i++) {
        __syncthreads();
        const int cur = i & 1;
        const bool more = (i + 1 < nChunks);
        if (more) {
            const float* ag2 = ag + (long)(i + 1) * KC;
            const float* bg2 = bg + (long)(i + 1) * KC;
#pragma unroll
            for (int g = 0; g < 4; g++) { av[g] = *(const float4*)(ag2 + g * 4); bv[g] = *(const float4*)(bg2 + g * 4); }
        }
        const uint32_t base = sb + (uint32_t)(cur * STAGE);
#pragma unroll
        for (int h = 0; h < 4; h++) {
            uint32_t ahi[2][4], alo[2][4], bf[4][2];
            const uint32_t aAddr = base + OFF_AH + (uint32_t)((wm * 32 + l16) * RSTR + (h * 16 + lh * 8) * 2);
            LDSM4(ahi[0], aAddr);
            LDSM4(ahi[1], aAddr + 16 * RSTR);
            LDSM4(alo[0], aAddr + ABYT);
            LDSM4(alo[1], aAddr + ABYT + 16 * RSTR);
            const uint32_t bAddr = base + OFF_BH + (uint32_t)((wn * 32 + bn) * RSTR + (h * 16 + bk) * 2);
            // B hi: two LDSM4 cover n0-15 and n16-31 of the warp's 32-n slab
            LDSM4(bf[0], bAddr);              // bf[0],bf[1] packed as 4 regs: n0-7, n8-15
            LDSM4(bf[2], bAddr + 16 * RSTR);  // n16-23, n24-31
#pragma unroll
            for (int mt = 0; mt < 2; mt++)
#pragma unroll
                for (int nn = 0; nn < 4; nn++) {
                    MMA(c[mt][nn], ahi[mt], (&bf[0][0]) + nn * 2);
                    MMA(c[mt][nn], alo[mt], (&bf[0][0]) + nn * 2);
                }
            // B lo (reuse bf regs)
            LDSM4(bf[0], bAddr + ABYT);
            LDSM4(bf[2], bAddr + ABYT + 16 * RSTR);
#pragma unroll
            for (int mt = 0; mt < 2; mt++)
#pragma unroll
                for (int nn = 0; nn < 4; nn++)
                    MMA(c[mt][nn], ahi[mt], (&bf[0][0]) + nn * 2);
        }
        if (more) {
            const uint32_t nb = sb + (uint32_t)(((i + 1) & 1) * STAGE);
            cvt_store8(nb + OFF_AH + sOff,      nb + OFF_AL + sOff,      av[0], av[1]);
            cvt_store8(nb + OFF_AH + sOff + 16, nb + OFF_AL + sOff + 16, av[2], av[3]);
            cvt_store8(nb + OFF_BH + sOff,      nb + OFF_BL + sOff,      bv[0], bv[1]);
            cvt_store8(nb + OFF_BH + sOff + 16, nb + OFF_BL + sOff + 16, bv[2], bv[3]);
        }
    }

    // epilogue
    const int mrow = wm * 32 + (lane >> 2);
    const int ncol = wn * 32 + (lane & 3) * 2;
#pragma unroll
    for (int mt = 0; mt < 2; mt++)
#pragma unroll
        for (int nn = 0; nn < 4; nn++) {
            float* p = Cb + (long)(mrow + mt * 16) * ldc + ncol + nn * 8;
            *(float2*)p = make_float2(c[mt][nn][0], c[mt][nn][1]);
            *(float2*)(p + (long)8 * ldc) = make_float2(c[mt][nn][2], c[mt][nn][3]);
        }
}

// ---------------------------------------------------------------------------
// wbases (b, n, k) -> g_wbT (b, k, n)
// ---------------------------------------------------------------------------
__global__ __launch_bounds__(256) void transpose_wb(const float* __restrict__ wb,
                                                    float* __restrict__ out) {
    __shared__ float t[32][33];
    const int b = blockIdx.z;
    const int n0 = blockIdx.x * 32, k0 = blockIdx.y * 32;
    const int x = threadIdx.x, y = threadIdx.y;
    const float* in = wb + (long)b * NPTS * MODES;
    float* o = out + (long)b * MODES * NPTS;
#pragma unroll
    for (int j = 0; j < 32; j += 8) t[y + j][x] = in[(long)(n0 + y + j) * MODES + k0 + x];
    __syncthreads();
#pragma unroll
    for (int j = 0; j < 32; j += 8) o[(long)(k0 + y + j) * NPTS + n0 + x] = t[x][y + j];
}

// split-K reduce
__global__ __launch_bounds__(256) void k1_reduce() {
    const int i = blockIdx.x * 256 + threadIdx.x;
    float s = 0.f;
#pragma unroll
    for (int p = 0; p < SPLIT1; p++) s += g_part[(size_t)p * (B_ * CIN * MODES) + i];
    g_xhat[i] = s;
}

// W2[r,k] = sum_j weights[r,j] * D[j,k]
__global__ __launch_bounds__(256) void k2a_w2(const float* __restrict__ weights,
                                              const float* __restrict__ D) {
    __shared__ float ws[64][KM];
    const int r0 = blockIdx.x * 64;
    const int k  = threadIdx.x;
    for (int idx = threadIdx.x; idx < 64 * KM; idx += 256)
        ws[idx >> 5][idx & 31] = weights[(size_t)r0 * KM + idx];
    float Dreg[KM];
#pragma unroll
    for (int j = 0; j < KM; j++) Dreg[j] = D[(size_t)j * MODES + k];
    __syncthreads();
    for (int r = 0; r < 64; r++) {
        float acc = 0.f;
#pragma unroll
        for (int j = 0; j < KM; j++) acc += ws[r][j] * Dreg[j];
        g_W2[(size_t)(r0 + r) * MODES + k] = acc;
    }
}

// y_hat[b,o,k] = sum_i x_hat[b,i,k] * W2[i,o,k]   (batch-inner: W2 read once)
__global__ __launch_bounds__(256) void k2b_yhat() {
    const int o0 = blockIdx.x * 4;
    const int k  = threadIdx.x;
    float acc[B_][4];
#pragma unroll
    for (int b = 0; b < B_; b++)
#pragma unroll
        for (int oo = 0; oo < 4; oo++) acc[b][oo] = 0.f;
    for (int i = 0; i < CIN; i++) {
        float w[4];
#pragma unroll
        for (int oo = 0; oo < 4; oo++)
            w[oo] = g_W2[((size_t)i * COUT + o0 + oo) * MODES + k];
#pragma unroll
        for (int b = 0; b < B_; b++) {
            const float xv = g_xhat[((size_t)b * CIN + i) * MODES + k];
#pragma unroll
            for (int oo = 0; oo < 4; oo++) acc[b][oo] += xv * w[oo];
        }
    }
#pragma unroll
    for (int b = 0; b < B_; b++)
#pragma unroll
        for (int oo = 0; oo < 4; oo++)
            g_yhat[((size_t)b * COUT + o0 + oo) * MODES + k] = acc[b][oo];
}

// ---------------------------------------------------------------------------
extern "C" void kernel_launch(void* const* d_in, const int* in_sizes, int n_in,
                              void* d_out, int out_size) {
    const float* x       = (const float*)d_in[0];   // (8, 128, 8192)
    const float* wbases  = (const float*)d_in[1];   // (8, 8192, 256)
    const float* bases   = (const float*)d_in[2];   // (8, 8192, 256)
    const float* weights = (const float*)d_in[3];   // (128, 128, 32)
    const float* Dm      = (const float*)d_in[4];   // (32, 256)
    float* y = (float*)d_out;                       // (8, 128, 8192)

    cudaFuncSetAttribute(gemm_bf16x3, cudaFuncAttributeMaxDynamicSharedMemorySize, SMEMSZ);

    void *p_part, *p_wbT, *p_yhat;
    cudaGetSymbolAddress(&p_part, g_part);
    cudaGetSymbolAddress(&p_wbT,  g_wbT);
    cudaGetSymbolAddress(&p_yhat, g_yhat);

    transpose_wb<<<dim3(NPTS / 32, MODES / 32, B_), dim3(32, 8)>>>(wbases, (float*)p_wbT);
    k2a_w2<<<CIN * COUT / 64, 256>>>(weights, Dm);

    // Stage 1: x_hat = x @ wbases  (M=128, N=256, K=8192; split-K=16 -> 256 CTAs)
    gemm_bf16x3<<<dim3(MODES / NT_, SPLIT1, B_), NTHR, SMEMSZ>>>(
        x, (const float*)p_wbT, (float*)p_part,
        NPTS, NPTS, MODES,
        (long)CIN * NPTS, (long)MODES * NPTS,
        (long)CIN * MODES, (long)B_ * CIN * MODES,
        (NPTS / SPLIT1) / KC);                      // 8 chunks
    k1_reduce<<<(B_ * CIN * MODES) / 256, 256>>>();

    // Stage 2
    k2b_yhat<<<COUT / 4, 256>>>();

    // Stage 3: y = y_hat @ bases^T  (M=128, N=8192, K=256 -> 512 CTAs)
    gemm_bf16x3<<<dim3(NPTS / NT_, 1, B_), NTHR, SMEMSZ>>>(
        (const float*)p_yhat, bases, y,
        MODES, MODES, NPTS,
        (long)COUT * MODES, (long)NPTS * MODES,
        (long)CIN * NPTS, 0L,
        MODES / KC);                                // 4 chunks
}

// round 5
// speedup vs baseline: 1.7855x; 1.3745x over previous
#include <cuda_runtime.h>
#include <cstdint>

// ---------------- problem constants ----------------
#define B_    8
#define CIN   128
#define COUT  128
#define NPTS  8192
#define KM    32
#define MODES 256
#define SPLIT1 16
#define KC    64          // K per chunk (fp32 elems)
#define NT_   128         // N tile
#define NTHR  512

// ---------------- device scratch ----------------
__device__ float g_part[SPLIT1 * B_ * CIN * MODES];   // 16.8 MB
__device__ float g_W2[CIN * COUT * MODES];            // 16.8 MB
__device__ float g_yhat[B_ * COUT * MODES];           // 1 MB

__device__ __forceinline__ uint32_t smem_u32(const void* p) {
    uint32_t a;
    asm("{ .reg .u64 t; cvta.to.shared.u64 t, %1; cvt.u32.u64 %0, t; }" : "=r"(a) : "l"(p));
    return a;
}
__device__ __forceinline__ uint32_t pk_bf16(float lo, float hi) {
    uint32_t r;
    asm("cvt.rn.bf16x2.f32 %0, %1, %2;" : "=r"(r) : "f"(hi), "f"(lo));
    return r;
}
// convert 8 consecutive fp32 to hi/lo bf16, store 16B each at hiA/loA
__device__ __forceinline__ void cvt_store8(uint32_t hiA, uint32_t loA, float4 v0, float4 v1) {
    uint32_t h0 = pk_bf16(v0.x, v0.y);
    uint32_t h1 = pk_bf16(v0.z, v0.w);
    uint32_t h2 = pk_bf16(v1.x, v1.y);
    uint32_t h3 = pk_bf16(v1.z, v1.w);
    float r0 = v0.x - __uint_as_float(h0 << 16);
    float r1 = v0.y - __uint_as_float(h0 & 0xffff0000u);
    float r2 = v0.z - __uint_as_float(h1 << 16);
    float r3 = v0.w - __uint_as_float(h1 & 0xffff0000u);
    float r4 = v1.x - __uint_as_float(h2 << 16);
    float r5 = v1.y - __uint_as_float(h2 & 0xffff0000u);
    float r6 = v1.z - __uint_as_float(h3 << 16);
    float r7 = v1.w - __uint_as_float(h3 & 0xffff0000u);
    uint32_t l0 = pk_bf16(r0, r1), l1 = pk_bf16(r2, r3);
    uint32_t l2 = pk_bf16(r4, r5), l3 = pk_bf16(r6, r7);
    asm volatile("st.shared.v4.b32 [%0], {%1,%2,%3,%4};" :: "r"(hiA), "r"(h0), "r"(h1), "r"(h2), "r"(h3));
    asm volatile("st.shared.v4.b32 [%0], {%1,%2,%3,%4};" :: "r"(loA), "r"(l0), "r"(l1), "r"(l2), "r"(l3));
}

#define LDSM4(r, addr) \
    asm volatile("ldmatrix.sync.aligned.m8n8.x4.shared.b16 {%0,%1,%2,%3}, [%4];" \
        : "=r"((r)[0]), "=r"((r)[1]), "=r"((r)[2]), "=r"((r)[3]) : "r"(addr))
#define LDSM4T(r, addr) \
    asm volatile("ldmatrix.sync.aligned.m8n8.x4.trans.shared.b16 {%0,%1,%2,%3}, [%4];" \
        : "=r"((r)[0]), "=r"((r)[1]), "=r"((r)[2]), "=r"((r)[3]) : "r"(addr))
#define MMA(c, a, bq) \
    asm volatile("mma.sync.aligned.m16n8k16.row.col.f32.bf16.bf16.f32 " \
        "{%0,%1,%2,%3}, {%4,%5,%6,%7}, {%8,%9}, {%0,%1,%2,%3};" \
        : "+f"((c)[0]), "+f"((c)[1]), "+f"((c)[2]), "+f"((c)[3]) \
        : "r"((a)[0]), "r"((a)[1]), "r"((a)[2]), "r"((a)[3]), "r"((bq)[0]), "r"((bq)[1]))

// ===========================================================================
// GEMM variant NT (stage 3): both A and B rows K-contiguous.
// CTA 128x128, 16 warps (4m x 4n), warp 32x32, KC=64, double buffered.
// ===========================================================================
#define RSTR   144
#define ABYT   (128 * RSTR)                    // 18432
#define NT_OFF_AH 0
#define NT_OFF_AL (ABYT)
#define NT_OFF_BH (2 * ABYT)
#define NT_OFF_BL (3 * ABYT)
#define NT_STAGE  (4 * ABYT)                   // 73728
#define NT_SMEM   (2 * NT_STAGE)               // 147456

__global__ __launch_bounds__(NTHR, 1) void gemm_nt(
    const float* __restrict__ A, const float* __restrict__ B, float* __restrict__ C,
    int lda, int ldb, int ldc,
    long sA, long sB, long sCb, int nChunks)
{
    extern __shared__ __align__(16) char smem[];
    const uint32_t sb = smem_u32(smem);
    const int tid = threadIdx.x, wid = tid >> 5, lane = tid & 31;
    const int nt = blockIdx.x, b = blockIdx.z;

    const float* Ab = A + (long)b * sA;
    const float* Bb = B + (long)b * sB + (long)nt * NT_ * ldb;
    float* Cb = C + (long)b * sCb + (long)nt * NT_;

    const int srow = tid >> 2, sk = (tid & 3) * 16;
    const float* ag = Ab + (long)srow * lda + sk;
    const float* bg = Bb + (long)srow * ldb + sk;
    const uint32_t sOff = (uint32_t)(srow * RSTR + sk * 2);

    const int wm = wid >> 2, wn = wid & 3;
    const int l16 = lane & 15, lh = lane >> 4;
    const int bn = ((lane >> 4) & 1) * 8 + (lane & 7);
    const int bk = ((lane >> 3) & 1) * 8;

    float c[2][4][4];
#pragma unroll
    for (int i = 0; i < 2; i++)
#pragma unroll
        for (int j = 0; j < 4; j++)
#pragma unroll
            for (int q = 0; q < 4; q++) c[i][j][q] = 0.f;

    float4 av[4], bv[4];
#pragma unroll
    for (int g = 0; g < 4; g++) { av[g] = *(const float4*)(ag + g * 4); bv[g] = *(const float4*)(bg + g * 4); }
    cvt_store8(sb + NT_OFF_AH + sOff,      sb + NT_OFF_AL + sOff,      av[0], av[1]);
    cvt_store8(sb + NT_OFF_AH + sOff + 16, sb + NT_OFF_AL + sOff + 16, av[2], av[3]);
    cvt_store8(sb + NT_OFF_BH + sOff,      sb + NT_OFF_BL + sOff,      bv[0], bv[1]);
    cvt_store8(sb + NT_OFF_BH + sOff + 16, sb + NT_OFF_BL + sOff + 16, bv[2], bv[3]);

    for (int i = 0; i < nChunks; i++) {
        __syncthreads();
        const int cur = i & 1;
        const bool more = (i + 1 < nChunks);
        if (more) {
            const float* ag2 = ag + (long)(i + 1) * KC;
            const float* bg2 = bg + (long)(i + 1) * KC;
#pragma unroll
            for (int g = 0; g < 4; g++) { av[g] = *(const float4*)(ag2 + g * 4); bv[g] = *(const float4*)(bg2 + g * 4); }
        }
        const uint32_t base = sb + (uint32_t)(cur * NT_STAGE);
#pragma unroll
        for (int h = 0; h < 4; h++) {
            uint32_t ahi[2][4], alo[2][4], bf[4][2];
            const uint32_t aAddr = base + NT_OFF_AH + (uint32_t)((wm * 32 + l16) * RSTR + (h * 16 + lh * 8) * 2);
            LDSM4(ahi[0], aAddr);
            LDSM4(ahi[1], aAddr + 16 * RSTR);
            LDSM4(alo[0], aAddr + ABYT);
            LDSM4(alo[1], aAddr + ABYT + 16 * RSTR);
            const uint32_t bAddr = base + NT_OFF_BH + (uint32_t)((wn * 32 + bn) * RSTR + (h * 16 + bk) * 2);
            LDSM4(bf[0], bAddr);
            LDSM4(bf[2], bAddr + 16 * RSTR);
#pragma unroll
            for (int mt = 0; mt < 2; mt++)
#pragma unroll
                for (int nn = 0; nn < 4; nn++) {
                    MMA(c[mt][nn], ahi[mt], (&bf[0][0]) + nn * 2);
                    MMA(c[mt][nn], alo[mt], (&bf[0][0]) + nn * 2);
                }
            LDSM4(bf[0], bAddr + ABYT);
            LDSM4(bf[2], bAddr + ABYT + 16 * RSTR);
#pragma unroll
            for (int mt = 0; mt < 2; mt++)
#pragma unroll
                for (int nn = 0; nn < 4; nn++)
                    MMA(c[mt][nn], ahi[mt], (&bf[0][0]) + nn * 2);
        }
        if (more) {
            const uint32_t nb = sb + (uint32_t)(((i + 1) & 1) * NT_STAGE);
            cvt_store8(nb + NT_OFF_AH + sOff,      nb + NT_OFF_AL + sOff,      av[0], av[1]);
            cvt_store8(nb + NT_OFF_AH + sOff + 16, nb + NT_OFF_AL + sOff + 16, av[2], av[3]);
            cvt_store8(nb + NT_OFF_BH + sOff,      nb + NT_OFF_BL + sOff,      bv[0], bv[1]);
            cvt_store8(nb + NT_OFF_BH + sOff + 16, nb + NT_OFF_BL + sOff + 16, bv[2], bv[3]);
        }
    }

    const int mrow = wm * 32 + (lane >> 2);
    const int ncol = wn * 32 + (lane & 3) * 2;
#pragma unroll
    for (int mt = 0; mt < 2; mt++)
#pragma unroll
        for (int nn = 0; nn < 4; nn++) {
            float* p = Cb + (long)(mrow + mt * 16) * ldc + ncol + nn * 8;
            *(float2*)p = make_float2(c[mt][nn][0], c[mt][nn][1]);
            *(float2*)(p + (long)8 * ldc) = make_float2(c[mt][nn][2], c[mt][nn][3]);
        }
}

// ===========================================================================
// GEMM variant TB (stage 1): A rows K-contiguous; B source is [k][n]
// (wbases: n_red rows, modes contiguous) staged as-is, fragments via
// ldmatrix.trans. CTA 128x128(modes), KC=64, split-K grid dim y.
// ===========================================================================
#define BRSTR  272                              // 128 modes*2B + 16B pad
#define TB_ABYT (128 * RSTR)                    // 18432 per A half
#define TB_BBYT (KC * BRSTR)                    // 17408 per B half
#define TB_OFF_AH 0
#define TB_OFF_AL (TB_ABYT)
#define TB_OFF_BH (2 * TB_ABYT)
#define TB_OFF_BL (2 * TB_ABYT + TB_BBYT)
#define TB_STAGE  (2 * TB_ABYT + 2 * TB_BBYT)   // 71680
#define TB_SMEM   (2 * TB_STAGE)                // 143360

__global__ __launch_bounds__(NTHR, 1) void gemm_tb(
    const float* __restrict__ A, const float* __restrict__ B, float* __restrict__ C,
    int nChunks)
{
    extern __shared__ __align__(16) char smem[];
    const uint32_t sb = smem_u32(smem);
    const int tid = threadIdx.x, wid = tid >> 5, lane = tid & 31;
    const int nt = blockIdx.x, sp = blockIdx.y, b = blockIdx.z;
    const long k0 = (long)sp * nChunks * KC;

    const float* Ab = A + (long)b * CIN * NPTS + k0;                       // x
    const float* Bb = B + (long)b * NPTS * MODES + k0 * MODES + nt * NT_;  // wbases
    float* Cb = C + ((long)sp * B_ + b) * CIN * MODES + nt * NT_;          // partials

    // A staging: 128 rows x 64 k
    const int srow = tid >> 2, sk = (tid & 3) * 16;
    const float* ag = Ab + (long)srow * NPTS + sk;
    const uint32_t aOff = (uint32_t)(srow * RSTR + sk * 2);
    // B staging: 64 k-rows x 128 modes
    const int brow = tid >> 3, bm = (tid & 7) * 16;
    const float* bg = Bb + (long)brow * MODES + bm;
    const uint32_t bOff = (uint32_t)(brow * BRSTR + bm * 2);

    const int wm = wid >> 2, wn = wid & 3;
    const int l16 = lane & 15, lh = lane >> 4;
    // B trans-ldmatrix lane addressing: k row + n column start
    const int tkl = ((lane >> 3) & 1) * 8 + (lane & 7);
    const int tnl = (lane >> 4) * 8;

    float c[2][4][4];
#pragma unroll
    for (int i = 0; i < 2; i++)
#pragma unroll
        for (int j = 0; j < 4; j++)
#pragma unroll
            for (int q = 0; q < 4; q++) c[i][j][q] = 0.f;

    float4 av[4], bv[4];
#pragma unroll
    for (int g = 0; g < 4; g++) { av[g] = *(const float4*)(ag + g * 4); bv[g] = *(const float4*)(bg + g * 4); }
    cvt_store8(sb + TB_OFF_AH + aOff,      sb + TB_OFF_AL + aOff,      av[0], av[1]);
    cvt_store8(sb + TB_OFF_AH + aOff + 16, sb + TB_OFF_AL + aOff + 16, av[2], av[3]);
    cvt_store8(sb + TB_OFF_BH + bOff,      sb + TB_OFF_BL + bOff,      bv[0], bv[1]);
    cvt_store8(sb + TB_OFF_BH + bOff + 16, sb + TB_OFF_BL + bOff + 16, bv[2], bv[3]);

    for (int i = 0; i < nChunks; i++) {
        __syncthreads();
        const int cur = i & 1;
        const bool more = (i + 1 < nChunks);
        if (more) {
            const float* ag2 = ag + (long)(i + 1) * KC;
            const float* bg2 = bg + (long)(i + 1) * KC * MODES;
#pragma unroll
            for (int g = 0; g < 4; g++) { av[g] = *(const float4*)(ag2 + g * 4); bv[g] = *(const float4*)(bg2 + g * 4); }
        }
        const uint32_t base = sb + (uint32_t)(cur * TB_STAGE);
#pragma unroll
        for (int h = 0; h < 4; h++) {
            uint32_t ahi[2][4], alo[2][4], bf[4][2];
            const uint32_t aAddr = base + TB_OFF_AH + (uint32_t)((wm * 32 + l16) * RSTR + (h * 16 + lh * 8) * 2);
            LDSM4(ahi[0], aAddr);
            LDSM4(ahi[1], aAddr + 16 * RSTR);
            LDSM4(alo[0], aAddr + TB_ABYT);
            LDSM4(alo[1], aAddr + TB_ABYT + 16 * RSTR);
            // B hi: two trans-LDSM4 cover modes wn*32..+15 and +16..+31
            const uint32_t bAddr = base + TB_OFF_BH + (uint32_t)((h * 16 + tkl) * BRSTR + (wn * 32 + tnl) * 2);
            LDSM4T(bf[0], bAddr);            // nn0 (n0-7), nn1 (n8-15)
            LDSM4T(bf[2], bAddr + 16 * 2);   // nn2 (n16-23), nn3 (n24-31)
#pragma unroll
            for (int mt = 0; mt < 2; mt++)
#pragma unroll
                for (int nn = 0; nn < 4; nn++) {
                    MMA(c[mt][nn], ahi[mt], (&bf[0][0]) + nn * 2);
                    MMA(c[mt][nn], alo[mt], (&bf[0][0]) + nn * 2);
                }
            LDSM4T(bf[0], bAddr + TB_BBYT);
            LDSM4T(bf[2], bAddr + TB_BBYT + 16 * 2);
#pragma unroll
            for (int mt = 0; mt < 2; mt++)
#pragma unroll
                for (int nn = 0; nn < 4; nn++)
                    MMA(c[mt][nn], ahi[mt], (&bf[0][0]) + nn * 2);
        }
        if (more) {
            const uint32_t nb = sb + (uint32_t)(((i + 1) & 1) * TB_STAGE);
            cvt_store8(nb + TB_OFF_AH + aOff,      nb + TB_OFF_AL + aOff,      av[0], av[1]);
            cvt_store8(nb + TB_OFF_AH + aOff + 16, nb + TB_OFF_AL + aOff + 16, av[2], av[3]);
            cvt_store8(nb + TB_OFF_BH + bOff,      nb + TB_OFF_BL + bOff,      bv[0], bv[1]);
            cvt_store8(nb + TB_OFF_BH + bOff + 16, nb + TB_OFF_BL + bOff + 16, bv[2], bv[3]);
        }
    }

    const int mrow = wm * 32 + (lane >> 2);
    const int ncol = wn * 32 + (lane & 3) * 2;
#pragma unroll
    for (int mt = 0; mt < 2; mt++)
#pragma unroll
        for (int nn = 0; nn < 4; nn++) {
            float* p = Cb + (long)(mrow + mt * 16) * MODES + ncol + nn * 8;
            *(float2*)p = make_float2(c[mt][nn][0], c[mt][nn][1]);
            *(float2*)(p + (long)8 * MODES) = make_float2(c[mt][nn][2], c[mt][nn][3]);
        }
}

// W2[r,k] = sum_j weights[r,j] * D[j,k]
__global__ __launch_bounds__(256) void k2a_w2(const float* __restrict__ weights,
                                              const float* __restrict__ D) {
    __shared__ float ws[64][KM];
    const int r0 = blockIdx.x * 64;
    const int k  = threadIdx.x;
    for (int idx = threadIdx.x; idx < 64 * KM; idx += 256)
        ws[idx >> 5][idx & 31] = weights[(size_t)r0 * KM + idx];
    float Dreg[KM];
#pragma unroll
    for (int j = 0; j < KM; j++) Dreg[j] = D[(size_t)j * MODES + k];
    __syncthreads();
    for (int r = 0; r < 64; r++) {
        float acc = 0.f;
#pragma unroll
        for (int j = 0; j < KM; j++) acc += ws[r][j] * Dreg[j];
        g_W2[(size_t)(r0 + r) * MODES + k] = acc;
    }
}

// Fused split-K reduce + channel mixing. One block per mode k:
//   X[b][i] = sum_p part[p][b][i][k]   (smem)
//   yhat[b][o][k] = sum_i X[b][i] * W2[i][o][k]
__global__ __launch_bounds__(256) void k2b_fused() {
    const int k = blockIdx.x;
    __shared__ float xs[B_][CIN];   // 4 KB
    for (int idx = threadIdx.x; idx < B_ * CIN; idx += 256) {
        float s = 0.f;
#pragma unroll
        for (int p = 0; p < SPLIT1; p++)
            s += g_part[(size_t)p * (B_ * CIN * MODES) + (size_t)idx * MODES + k];
        xs[idx >> 7][idx & 127] = s;
    }
    __syncthreads();
    const int o  = threadIdx.x & 127;
    const int bh = (threadIdx.x >> 7) * 4;   // 0 or 4
    float acc[4] = {0.f, 0.f, 0.f, 0.f};
#pragma unroll 4
    for (int i = 0; i < CIN; i++) {
        const float w = g_W2[((size_t)i * COUT + o) * MODES + k];
#pragma unroll
        for (int bb = 0; bb < 4; bb++) acc[bb] += xs[bh + bb][i] * w;
    }
#pragma unroll
    for (int bb = 0; bb < 4; bb++)
        g_yhat[((size_t)(bh + bb) * COUT + o) * MODES + k] = acc[bb];
}

// ---------------------------------------------------------------------------
extern "C" void kernel_launch(void* const* d_in, const int* in_sizes, int n_in,
                              void* d_out, int out_size) {
    const float* x       = (const float*)d_in[0];   // (8, 128, 8192)
    const float* wbases  = (const float*)d_in[1];   // (8, 8192, 256)
    const float* bases   = (const float*)d_in[2];   // (8, 8192, 256)
    const float* weights = (const float*)d_in[3];   // (128, 128, 32)
    const float* Dm      = (const float*)d_in[4];   // (32, 256)
    float* y = (float*)d_out;                       // (8, 128, 8192)

    cudaFuncSetAttribute(gemm_nt, cudaFuncAttributeMaxDynamicSharedMemorySize, NT_SMEM);
    cudaFuncSetAttribute(gemm_tb, cudaFuncAttributeMaxDynamicSharedMemorySize, TB_SMEM);

    void *p_part, *p_yhat;
    cudaGetSymbolAddress(&p_part, g_part);
    cudaGetSymbolAddress(&p_yhat, g_yhat);

    // W2 precompute
    k2a_w2<<<CIN * COUT / 64, 256>>>(weights, Dm);

    // Stage 1: x_hat partials = x @ wbases  (split-K=16 -> 256 CTAs)
    gemm_tb<<<dim3(MODES / NT_, SPLIT1, B_), NTHR, TB_SMEM>>>(
        x, wbases, (float*)p_part, (NPTS / SPLIT1) / KC);   // 8 chunks

    // Stage 2: fused reduce + channel mixing
    k2b_fused<<<MODES, 256>>>();

    // Stage 3: y = y_hat @ bases^T  (512 CTAs)
    gemm_nt<<<dim3(NPTS / NT_, 1, B_), NTHR, NT_SMEM>>>(
        (const float*)p_yhat, bases, y,
        MODES, MODES, NPTS,
        (long)COUT * MODES, (long)NPTS * MODES, (long)CIN * NPTS,
        MODES / KC);                                        // 4 chunks
}